// round 14
// baseline (speedup 1.0000x reference)
#include <cuda_runtime.h>

// ============================================================================
// 2-layer tanh RNN, B=32, L=2048, H=512 — v13: v12 + rebalanced critical chain.
//
// 128 persistent CTAs (1/SM), 512 threads (16 warps):
//   CTA 0..63   : layer 0 (A), output cols [cta*8, cta*8+8)
//   CTA 64..127 : layer 1 (B), cols [(cta-64)*8, ...)
//
// Warp split by SIDE with K-half rebalance (v13):
//   A early (0..7): x-side full-K (ungated) -> gate AL[t-1] -> h-side K-LO
//                   (gate hidden behind ~1400 cyc of x-FMA)
//   A late  (8..15): gate AH[t-1] (+flagB[t-8]) -> h-side K-HI (only 128
//                   FMA2 on the critical chain) -> reduce -> combine -> tanh
//                   -> publish ring + flag
//   B early (0..7): ring-side full-K (gate AL[t]&AH[t]) -> h1-side K-LO
//                   (gate flagB[t-1] hidden behind ring FMA)
//   B late  (8..15): gate flagB[t-1] -> h1-side K-HI -> ... -> publish out
//                   (B-late never waits on A at all)
// Early + gated-half accumulate into the SAME acc registers (same outputs,
// different K) -> reduce/comb volume unchanged from v12.
// Pair (wp, 8+wp) covers rows 4wp..4wp+3; combine via BAR64(3+wp) + comb
// double buffer (parity t&1). Publish: STG -> BAR256(2) -> w8.ln0 rel_add.
// Flags: flagAL/AH[t] (A col-halves = B/A K-halves, tgt 32), flagB[t] (tgt 64).
// Dataflow: L0 h -> 8-slot global ring; L1 h -> d_out. __ldcg cross-SM reads.
// fp32 packed fma.rn.f32x2, numerics identical to v2..v12.
// ============================================================================

#define BB 32
#define LL 2048
#define HH 512
#define GA 64
#define GB 64
#define NTHR 512

__device__ float g_ring[8 * BB * HH];   // layer-0 h ring, 8 slots, 512 KB
__device__ int   g_flagAL[LL];          // A cols [0,256)   done at t (tgt 32)
__device__ int   g_flagAH[LL];          // A cols [256,512) done at t (tgt 32)
__device__ int   g_flagB[LL];           // B done at t (tgt 64)

__device__ __forceinline__ int acq(const int* p) {
    int v;
    asm volatile("ld.acquire.gpu.global.b32 %0, [%1];" : "=r"(v) : "l"(p) : "memory");
    return v;
}
__device__ __forceinline__ void rel_add(int* p) {
    asm volatile("red.release.gpu.global.add.u32 [%0], %1;"
                 :: "l"(p), "r"(1u) : "memory");
}
#define BAR256(id) asm volatile("bar.sync %0, 256;" :: "r"(id) : "memory")
#define BAR64(id)  asm volatile("bar.sync %0, 64;"  :: "r"(id) : "memory")

#define FMA2(d, a, w) asm volatile("fma.rn.f32x2 %0, %1, %2, %0;" \
                                   : "+l"(d) : "l"(a), "l"(w))

__device__ __forceinline__ unsigned long long pack2(float v) {
    unsigned long long r;
    asm("mov.b64 %0, {%1,%1};" : "=l"(r) : "f"(v));
    return r;
}

__global__ void zero_flags_kernel() {
    int i = blockIdx.x * blockDim.x + threadIdx.x;
    if (i < LL) { g_flagAL[i] = 0; g_flagAH[i] = 0; g_flagB[i] = 0; }
}

// Full-K accumulation of ONE side: all 16 LDG.128 batched up front (MLP=16).
// acc[b*4+q] packs cols (2q,2q+1) for row b0+b. Weights lane-interleaved:
// [(i4*4+e)*32+ln] = k = 128*i4 + 4*ln + e.
__device__ __forceinline__ void accum_both(
    unsigned long long acc[16],
    const ulonglong2* __restrict__ wA, const ulonglong2* __restrict__ wB,
    const float* __restrict__ p, long long stride, int b0, int ln, bool cg)
{
    float4 v[4][4];   // [i4][b]
    #pragma unroll
    for (int i4 = 0; i4 < 4; i4++)
        #pragma unroll
        for (int b = 0; b < 4; b++) {
            const float4* a = (const float4*)(p + (long long)(b0 + b) * stride
                                              + 128 * i4 + 4 * ln);
            v[i4][b] = cg ? __ldcg(a) : *a;
        }
    #pragma unroll
    for (int i4 = 0; i4 < 4; i4++)
        #pragma unroll
        for (int e = 0; e < 4; e++) {
            ulonglong2 a  = wA[(i4 * 4 + e) * 32 + ln];
            ulonglong2 bq = wB[(i4 * 4 + e) * 32 + ln];
            #pragma unroll
            for (int b = 0; b < 4; b++) {
                float xv = (e == 0) ? v[i4][b].x : (e == 1) ? v[i4][b].y
                         : (e == 2) ? v[i4][b].z : v[i4][b].w;
                unsigned long long xp = pack2(xv);
                FMA2(acc[b * 4 + 0], xp, a.x);
                FMA2(acc[b * 4 + 1], xp, a.y);
                FMA2(acc[b * 4 + 2], xp, bq.x);
                FMA2(acc[b * 4 + 3], xp, bq.y);
            }
        }
}

// Half-K accumulation (hk = 0: k<256, hk = 1: k>=256) of one side, 8 LDG.128.
__device__ __forceinline__ void accum_half(
    unsigned long long acc[16],
    const ulonglong2* __restrict__ wA, const ulonglong2* __restrict__ wB,
    const float* __restrict__ p, long long stride, int b0, int ln,
    int hk, bool cg)
{
    float4 v[2][4];
    #pragma unroll
    for (int j = 0; j < 2; j++) {
        int i4 = 2 * hk + j;
        #pragma unroll
        for (int b = 0; b < 4; b++) {
            const float4* a = (const float4*)(p + (long long)(b0 + b) * stride
                                              + 128 * i4 + 4 * ln);
            v[j][b] = cg ? __ldcg(a) : *a;
        }
    }
    #pragma unroll
    for (int j = 0; j < 2; j++) {
        int i4 = 2 * hk + j;
        #pragma unroll
        for (int e = 0; e < 4; e++) {
            ulonglong2 a  = wA[(i4 * 4 + e) * 32 + ln];
            ulonglong2 bq = wB[(i4 * 4 + e) * 32 + ln];
            #pragma unroll
            for (int b = 0; b < 4; b++) {
                float xv = (e == 0) ? v[j][b].x : (e == 1) ? v[j][b].y
                         : (e == 2) ? v[j][b].z : v[j][b].w;
                unsigned long long xp = pack2(xv);
                FMA2(acc[b * 4 + 0], xp, a.x);
                FMA2(acc[b * 4 + 1], xp, a.y);
                FMA2(acc[b * 4 + 2], xp, bq.x);
                FMA2(acc[b * 4 + 3], xp, bq.y);
            }
        }
    }
}

// Per-warp transpose-reduce over the 32-lane K split.
__device__ __forceinline__ float reduce32(const unsigned long long acc[16],
                                          float* redw, int ln)
{
    #pragma unroll
    for (int i = 0; i < 16; i++) {
        float2 v = *reinterpret_cast<const float2*>(&acc[i]);
        int a = (i >> 2) * 8 + (i & 3) * 2;
        redw[ln * 33 + a]     = v.x;
        redw[ln * 33 + a + 1] = v.y;
    }
    __syncwarp();
    float s0 = 0.f, s1 = 0.f, s2 = 0.f, s3 = 0.f;
    #pragma unroll
    for (int a = 0; a < 32; a += 4) {
        s0 += redw[(a + 0) * 33 + ln];
        s1 += redw[(a + 1) * 33 + ln];
        s2 += redw[(a + 2) * 33 + ln];
        s3 += redw[(a + 3) * 33 + ln];
    }
    __syncwarp();
    return (s0 + s1) + (s2 + s3);
}

__global__ __launch_bounds__(NTHR, 1) void rnn_kernel(
    const float* __restrict__ x,   const float* __restrict__ h0in,
    const float* __restrict__ Wi,  const float* __restrict__ bi,
    const float* __restrict__ Wh,  const float* __restrict__ bh,
    float* __restrict__ out, int write_final)
{
    extern __shared__ float smem[];
    ulonglong2* sWiA = (ulonglong2*)smem;      // [512] Wi cols 0-3
    ulonglong2* sWiB = sWiA + HH;              // [512] Wi cols 4-7
    ulonglong2* sWhA = sWiB + HH;              // [512] Wh cols 0-3
    ulonglong2* sWhB = sWhA + HH;              // [512] Wh cols 4-7
    float*      red  = (float*)(sWhB + HH);    // [16 warps][32][33]
    float*      comb = red + 16 * 32 * 33;     // [2][256] early->late combine

    const int  cta   = blockIdx.x;
    const bool isA   = (cta < GA);
    const int  layer = isA ? 0 : 1;
    const int  c0    = (isA ? cta : cta - GA) * 8;
    const int  tid   = threadIdx.x;
    const int  w     = tid >> 5;
    const int  ln    = tid & 31;
    const int  late  = w >> 3;          // 0 = early side, 1 = late (critical)
    const int  wp    = w & 7;           // pair index
    const int  b0    = 4 * wp;

    // ---- stage weight slices once: idx(k) = ((k>>7)*4 + (k&3))*32 + ((k>>2)&31)
    {
        const float* wi_g = Wi + (size_t)layer * HH * HH + c0;
        const float* wh_g = Wh + (size_t)layer * HH * HH + c0;
        for (int k = tid; k < HH; k += NTHR) {
            int idx = ((k >> 7) * 4 + (k & 3)) * 32 + ((k >> 2) & 31);
            const ulonglong2* ri = (const ulonglong2*)(wi_g + (size_t)k * HH);
            const ulonglong2* rh = (const ulonglong2*)(wh_g + (size_t)k * HH);
            sWiA[idx] = ri[0];  sWiB[idx] = ri[1];
            sWhA[idx] = rh[0];  sWhB[idx] = rh[1];
        }
    }
    __syncthreads();    // one-time; no CTA-wide barrier in the loop

    const int   myb  = b0 + (ln >> 3);
    const int   myc  = c0 + (ln & 7);
    const float bias = bi[layer * HH + myc] + bh[layer * HH + myc];
    float* redw = red + w * (32 * 33);
    const int ci = wp * 32 + ln;

    if (isA) {
        if (!late) {
            // ===== A EARLY: x-side full-K (ungated) + h-side K-LO =====
            #pragma unroll 1
            for (int t = 0; t < LL; t++) {
                unsigned long long acc[16];
                #pragma unroll
                for (int i = 0; i < 16; i++) acc[i] = 0ull;
                accum_both(acc, sWiA, sWiB, x + (long long)t * HH,
                           (long long)LL * HH, b0, ln, false);
                if (t == 0) {
                    accum_half(acc, sWhA, sWhB, h0in, HH, b0, ln, 0, false);
                } else {
                    // gate AL[t-1] — usually open after the x-side FMA
                    if (w == 0) { while (acq(&g_flagAL[t-1]) < 32) {} }
                    BAR256(1);
                    accum_half(acc, sWhA, sWhB,
                               g_ring + ((t - 1) & 7) * (BB * HH),
                               HH, b0, ln, 0, true);
                }
                comb[(t & 1) * 256 + ci] = reduce32(acc, redw, ln);
                BAR64(3 + wp);
            }
        } else {
            // ===== A LATE (critical): h-side K-HI only + publish =====
            #pragma unroll 1
            for (int t = 0; t < LL; t++) {
                unsigned long long acc[16];
                #pragma unroll
                for (int i = 0; i < 16; i++) acc[i] = 0ull;
                if (t == 0) {
                    accum_half(acc, sWhA, sWhB, h0in, HH, b0, ln, 1, false);
                } else {
                    if (w == 8) {
                        if (t >= 8) { while (acq(&g_flagAH[t-1]) < 32 ||
                                             acq(&g_flagB[t-8])  < GB) {} }
                        else        { while (acq(&g_flagAH[t-1]) < 32) {} }
                    }
                    BAR256(2);
                    accum_half(acc, sWhA, sWhB,
                               g_ring + ((t - 1) & 7) * (BB * HH),
                               HH, b0, ln, 1, true);
                }
                float psum = reduce32(acc, redw, ln);
                BAR64(3 + wp);   // early partial (x + h-lo) ready in comb
                float hval = tanhf(psum + comb[(t & 1) * 256 + ci] + bias);
                g_ring[(t & 7) * (BB * HH) + myb * HH + myc] = hval;
                if (write_final && t == LL - 1)
                    out[(long long)BB * LL * HH + myb * HH + myc] = hval;
                BAR256(2);       // all late STGs issued
                if (w == 8 && ln == 0)
                    rel_add(cta < 32 ? &g_flagAL[t] : &g_flagAH[t]);
            }
        }
    } else {
        if (!late) {
            // ===== B EARLY: ring-side full-K + h1-side K-LO =====
            #pragma unroll 1
            for (int t = 0; t < LL; t++) {
                unsigned long long acc[16];
                #pragma unroll
                for (int i = 0; i < 16; i++) acc[i] = 0ull;
                if (w == 0) { while (acq(&g_flagAL[t]) < 32 ||
                                     acq(&g_flagAH[t]) < 32) {} }
                BAR256(1);
                accum_both(acc, sWiA, sWiB, g_ring + (t & 7) * (BB * HH),
                           HH, b0, ln, true);
                if (t == 0) {
                    accum_half(acc, sWhA, sWhB, h0in + BB * HH,
                               HH, b0, ln, 0, false);
                } else {
                    // flagB[t-1] — hidden behind the ring FMA above
                    if (w == 0) { while (acq(&g_flagB[t-1]) < GB) {} }
                    BAR256(1);
                    accum_half(acc, sWhA, sWhB, out + (long long)(t - 1) * HH,
                               (long long)LL * HH, b0, ln, 0, true);
                }
                comb[(t & 1) * 256 + ci] = reduce32(acc, redw, ln);
                BAR64(3 + wp);
            }
        } else {
            // ===== B LATE (critical): h1-side K-HI only + publish =====
            #pragma unroll 1
            for (int t = 0; t < LL; t++) {
                unsigned long long acc[16];
                #pragma unroll
                for (int i = 0; i < 16; i++) acc[i] = 0ull;
                if (t == 0) {
                    accum_half(acc, sWhA, sWhB, h0in + BB * HH,
                               HH, b0, ln, 1, false);
                } else {
                    if (w == 8) { while (acq(&g_flagB[t-1]) < GB) {} }
                    BAR256(2);
                    accum_half(acc, sWhA, sWhB, out + (long long)(t - 1) * HH,
                               (long long)LL * HH, b0, ln, 1, true);
                }
                float psum = reduce32(acc, redw, ln);
                BAR64(3 + wp);   // early partial (ring + h1-lo) ready
                float hval = tanhf(psum + comb[(t & 1) * 256 + ci] + bias);
                out[(long long)myb * LL * HH + (long long)t * HH + myc] = hval;
                if (write_final && t == LL - 1)
                    out[(long long)BB * LL * HH + BB * HH + myb * HH + myc] = hval;
                BAR256(2);       // all late STGs issued
                if (w == 8 && ln == 0) rel_add(&g_flagB[t]);
            }
        }
    }
}

extern "C" void kernel_launch(void* const* d_in, const int* in_sizes, int n_in,
                              void* d_out, int out_size)
{
    const float* x  = (const float*)d_in[0];
    const float* h0 = (const float*)d_in[1];
    const float* Wi = (const float*)d_in[2];
    const float* bi = (const float*)d_in[3];
    const float* Wh = (const float*)d_in[4];
    const float* bh = (const float*)d_in[5];
    float* out = (float*)d_out;

    int write_final = (out_size >= BB * LL * HH + 2 * BB * HH) ? 1 : 0;

    size_t smem = (size_t)(4 * HH * 16)                    // weights 32 KB
                + (size_t)(16 * 32 * 33) * sizeof(float)   // red    ~66 KB
                + (size_t)(2 * 256) * sizeof(float);       // comb     2 KB
    cudaFuncSetAttribute(rnn_kernel,
                         cudaFuncAttributeMaxDynamicSharedMemorySize, (int)smem);

    zero_flags_kernel<<<(LL + 255) / 256, 256>>>();
    rnn_kernel<<<GA + GB, NTHR, smem>>>(x, h0, Wi, bi, Wh, bh, out, write_final);
}

// round 15
// speedup vs baseline: 1.0108x; 1.0108x over previous
#include <cuda_runtime.h>

// ============================================================================
// 2-layer tanh RNN, B=32, L=2048, H=512 — v14: balanced side/K-half warp
// specialization + per-warp publication (v12 skeleton).
//
// 128 persistent CTAs (1/SM), 512 threads (16 warps):
//   CTA 0..63   : layer 0 (A), output cols [cta*8, cta*8+8)
//   CTA 64..127 : layer 1 (B), cols [(cta-64)*8, ...)
// Pair (wp, 8+wp) covers rows 4wp..4wp+3. EVERY warp: 256 FMA2/step.
//   A early (0..7):  x-LO 128 (ungated) -> gate AL[t-1] -> h-LO 128
//   A late  (8..15): x-HI 128 (ungated fill) -> gate AH[t-1] (+B[t-8])
//                    -> h-HI 128 -> reduce -> +comb -> tanh -> publish ring
//   B early (0..7):  gate AL[t] (open; A leads) -> ring-LO 128 (fills wait)
//                    -> gate B[t-1] -> h1-LO 128
//   B late  (8..15): gate AH[t] -> ring-HI 128 -> gate B[t-1] -> h1-HI 128
//                    -> reduce -> +comb -> tanh -> publish out
// Post-critical-gate FMA segment = 128 FMA2 everywhere (v12: 256).
// Ring K-halves match AL/AH producer cols, so each warp gates only on the
// half it reads.
//
// Publication v14: PER-WARP — each late warp: STG -> __syncwarp -> lane0
// red.release.gpu.add. Targets: AL/AH = 256 (8 warps x 32 CTAs), B = 512.
// (final BAR256 removed from the critical chain.)
// Gates: leader-warp poll (w0 / w8) + half-CTA named barrier (ids 1 / 2);
// pair combine via BAR64(3+wp) + comb double buffer (parity t&1).
// Dataflow: L0 h -> 8-slot global ring (reuse gate B[t-8]); L1 h -> d_out.
// __ldcg cross-SM reads. fp32 packed fma.rn.f32x2, numerics as v2..v13.
// ============================================================================

#define BB 32
#define LL 2048
#define HH 512
#define GA 64
#define GB 64
#define NTHR 512

__device__ float g_ring[8 * BB * HH];   // layer-0 h ring, 8 slots, 512 KB
__device__ int   g_flagAL[LL];          // A cols [0,256)   done at t (tgt 256)
__device__ int   g_flagAH[LL];          // A cols [256,512) done at t (tgt 256)
__device__ int   g_flagB[LL];           // B done at t (tgt 512)

__device__ __forceinline__ int acq(const int* p) {
    int v;
    asm volatile("ld.acquire.gpu.global.b32 %0, [%1];" : "=r"(v) : "l"(p) : "memory");
    return v;
}
__device__ __forceinline__ void rel_add(int* p) {
    asm volatile("red.release.gpu.global.add.u32 [%0], %1;"
                 :: "l"(p), "r"(1u) : "memory");
}
#define BAR256(id) asm volatile("bar.sync %0, 256;" :: "r"(id) : "memory")
#define BAR64(id)  asm volatile("bar.sync %0, 64;"  :: "r"(id) : "memory")

#define FMA2(d, a, w) asm volatile("fma.rn.f32x2 %0, %1, %2, %0;" \
                                   : "+l"(d) : "l"(a), "l"(w))

__device__ __forceinline__ unsigned long long pack2(float v) {
    unsigned long long r;
    asm("mov.b64 %0, {%1,%1};" : "=l"(r) : "f"(v));
    return r;
}

__global__ void zero_flags_kernel() {
    int i = blockIdx.x * blockDim.x + threadIdx.x;
    if (i < LL) { g_flagAL[i] = 0; g_flagAH[i] = 0; g_flagB[i] = 0; }
}

// Half-K accumulation (hk = 0: k<256, hk = 1: k>=256) of one side into
// acc[16] (acc[b*4+q] packs cols (2q,2q+1) for row b0+b). 8 LDG.128 batched
// up front. Weights lane-interleaved: [(i4*4+e)*32+ln] = k = 128*i4+4*ln+e.
__device__ __forceinline__ void accum_half(
    unsigned long long acc[16],
    const ulonglong2* __restrict__ wA, const ulonglong2* __restrict__ wB,
    const float* __restrict__ p, long long stride, int b0, int ln,
    int hk, bool cg)
{
    float4 v[2][4];
    #pragma unroll
    for (int j = 0; j < 2; j++) {
        int i4 = 2 * hk + j;
        #pragma unroll
        for (int b = 0; b < 4; b++) {
            const float4* a = (const float4*)(p + (long long)(b0 + b) * stride
                                              + 128 * i4 + 4 * ln);
            v[j][b] = cg ? __ldcg(a) : *a;
        }
    }
    #pragma unroll
    for (int j = 0; j < 2; j++) {
        int i4 = 2 * hk + j;
        #pragma unroll
        for (int e = 0; e < 4; e++) {
            ulonglong2 a  = wA[(i4 * 4 + e) * 32 + ln];
            ulonglong2 bq = wB[(i4 * 4 + e) * 32 + ln];
            #pragma unroll
            for (int b = 0; b < 4; b++) {
                float xv = (e == 0) ? v[j][b].x : (e == 1) ? v[j][b].y
                         : (e == 2) ? v[j][b].z : v[j][b].w;
                unsigned long long xp = pack2(xv);
                FMA2(acc[b * 4 + 0], xp, a.x);
                FMA2(acc[b * 4 + 1], xp, a.y);
                FMA2(acc[b * 4 + 2], xp, bq.x);
                FMA2(acc[b * 4 + 3], xp, bq.y);
            }
        }
    }
}

// Per-warp transpose-reduce over the 32-lane K split.
__device__ __forceinline__ float reduce32(const unsigned long long acc[16],
                                          float* redw, int ln)
{
    #pragma unroll
    for (int i = 0; i < 16; i++) {
        float2 v = *reinterpret_cast<const float2*>(&acc[i]);
        int a = (i >> 2) * 8 + (i & 3) * 2;
        redw[ln * 33 + a]     = v.x;
        redw[ln * 33 + a + 1] = v.y;
    }
    __syncwarp();
    float s0 = 0.f, s1 = 0.f, s2 = 0.f, s3 = 0.f;
    #pragma unroll
    for (int a = 0; a < 32; a += 4) {
        s0 += redw[(a + 0) * 33 + ln];
        s1 += redw[(a + 1) * 33 + ln];
        s2 += redw[(a + 2) * 33 + ln];
        s3 += redw[(a + 3) * 33 + ln];
    }
    __syncwarp();
    return (s0 + s1) + (s2 + s3);
}

__global__ __launch_bounds__(NTHR, 1) void rnn_kernel(
    const float* __restrict__ x,   const float* __restrict__ h0in,
    const float* __restrict__ Wi,  const float* __restrict__ bi,
    const float* __restrict__ Wh,  const float* __restrict__ bh,
    float* __restrict__ out, int write_final)
{
    extern __shared__ float smem[];
    ulonglong2* sWiA = (ulonglong2*)smem;      // [512] Wi cols 0-3
    ulonglong2* sWiB = sWiA + HH;              // [512] Wi cols 4-7
    ulonglong2* sWhA = sWiB + HH;              // [512] Wh cols 0-3
    ulonglong2* sWhB = sWhA + HH;              // [512] Wh cols 4-7
    float*      red  = (float*)(sWhB + HH);    // [16 warps][32][33]
    float*      comb = red + 16 * 32 * 33;     // [2][256] early->late combine

    const int  cta   = blockIdx.x;
    const bool isA   = (cta < GA);
    const int  layer = isA ? 0 : 1;
    const int  c0    = (isA ? cta : cta - GA) * 8;
    const int  tid   = threadIdx.x;
    const int  w     = tid >> 5;
    const int  ln    = tid & 31;
    const int  late  = w >> 3;          // 0 = early (K-lo), 1 = late (K-hi)
    const int  wp    = w & 7;           // pair index
    const int  b0    = 4 * wp;

    // ---- stage weight slices once: idx(k) = ((k>>7)*4 + (k&3))*32 + ((k>>2)&31)
    {
        const float* wi_g = Wi + (size_t)layer * HH * HH + c0;
        const float* wh_g = Wh + (size_t)layer * HH * HH + c0;
        for (int k = tid; k < HH; k += NTHR) {
            int idx = ((k >> 7) * 4 + (k & 3)) * 32 + ((k >> 2) & 31);
            const ulonglong2* ri = (const ulonglong2*)(wi_g + (size_t)k * HH);
            const ulonglong2* rh = (const ulonglong2*)(wh_g + (size_t)k * HH);
            sWiA[idx] = ri[0];  sWiB[idx] = ri[1];
            sWhA[idx] = rh[0];  sWhB[idx] = rh[1];
        }
    }
    __syncthreads();    // one-time; no CTA-wide barrier in the loop

    const int   myb  = b0 + (ln >> 3);
    const int   myc  = c0 + (ln & 7);
    const float bias = bi[layer * HH + myc] + bh[layer * HH + myc];
    float* redw = red + w * (32 * 33);
    const int ci = wp * 32 + ln;

    if (isA) {
        if (!late) {
            // ===== A EARLY: x-LO (ungated) -> gate AL[t-1] -> h-LO =====
            #pragma unroll 1
            for (int t = 0; t < LL; t++) {
                unsigned long long acc[16];
                #pragma unroll
                for (int i = 0; i < 16; i++) acc[i] = 0ull;
                accum_half(acc, sWiA, sWiB, x + (long long)t * HH,
                           (long long)LL * HH, b0, ln, 0, false);
                if (t == 0) {
                    accum_half(acc, sWhA, sWhB, h0in, HH, b0, ln, 0, false);
                } else {
                    if (w == 0) { while (acq(&g_flagAL[t-1]) < 256) {} }
                    BAR256(1);
                    accum_half(acc, sWhA, sWhB,
                               g_ring + ((t - 1) & 7) * (BB * HH),
                               HH, b0, ln, 0, true);
                }
                comb[(t & 1) * 256 + ci] = reduce32(acc, redw, ln);
                BAR64(3 + wp);
            }
        } else {
            // ===== A LATE: x-HI (fill) -> gate AH[t-1] -> h-HI -> publish ===
            #pragma unroll 1
            for (int t = 0; t < LL; t++) {
                unsigned long long acc[16];
                #pragma unroll
                for (int i = 0; i < 16; i++) acc[i] = 0ull;
                accum_half(acc, sWiA, sWiB, x + (long long)t * HH,
                           (long long)LL * HH, b0, ln, 1, false);
                if (t == 0) {
                    accum_half(acc, sWhA, sWhB, h0in, HH, b0, ln, 1, false);
                } else {
                    if (w == 8) {
                        if (t >= 8) { while (acq(&g_flagAH[t-1]) < 256 ||
                                             acq(&g_flagB[t-8])  < 512) {} }
                        else        { while (acq(&g_flagAH[t-1]) < 256) {} }
                    }
                    BAR256(2);
                    accum_half(acc, sWhA, sWhB,
                               g_ring + ((t - 1) & 7) * (BB * HH),
                               HH, b0, ln, 1, true);
                }
                float psum = reduce32(acc, redw, ln);
                BAR64(3 + wp);   // early partial (x-lo + h-lo) in comb
                float hval = tanhf(psum + comb[(t & 1) * 256 + ci] + bias);
                g_ring[(t & 7) * (BB * HH) + myb * HH + myc] = hval;
                if (write_final && t == LL - 1)
                    out[(long long)BB * LL * HH + myb * HH + myc] = hval;
                __syncwarp();    // this warp's STGs issued
                if (ln == 0)
                    rel_add(cta < 32 ? &g_flagAL[t] : &g_flagAH[t]);
            }
        }
    } else {
        if (!late) {
            // ===== B EARLY: gate AL[t] -> ring-LO -> gate B[t-1] -> h1-LO ===
            #pragma unroll 1
            for (int t = 0; t < LL; t++) {
                unsigned long long acc[16];
                #pragma unroll
                for (int i = 0; i < 16; i++) acc[i] = 0ull;
                if (w == 0) { while (acq(&g_flagAL[t]) < 256) {} }
                BAR256(1);
                accum_half(acc, sWiA, sWiB, g_ring + (t & 7) * (BB * HH),
                           HH, b0, ln, 0, true);
                if (t == 0) {
                    accum_half(acc, sWhA, sWhB, h0in + BB * HH,
                               HH, b0, ln, 0, false);
                } else {
                    if (w == 0) { while (acq(&g_flagB[t-1]) < 512) {} }
                    BAR256(1);
                    accum_half(acc, sWhA, sWhB, out + (long long)(t - 1) * HH,
                               (long long)LL * HH, b0, ln, 0, true);
                }
                comb[(t & 1) * 256 + ci] = reduce32(acc, redw, ln);
                BAR64(3 + wp);
            }
        } else {
            // ===== B LATE: gate AH[t] -> ring-HI -> gate B[t-1] -> h1-HI ====
            #pragma unroll 1
            for (int t = 0; t < LL; t++) {
                unsigned long long acc[16];
                #pragma unroll
                for (int i = 0; i < 16; i++) acc[i] = 0ull;
                if (w == 8) { while (acq(&g_flagAH[t]) < 256) {} }
                BAR256(2);
                accum_half(acc, sWiA, sWiB, g_ring + (t & 7) * (BB * HH),
                           HH, b0, ln, 1, true);
                if (t == 0) {
                    accum_half(acc, sWhA, sWhB, h0in + BB * HH,
                               HH, b0, ln, 1, false);
                } else {
                    if (w == 8) { while (acq(&g_flagB[t-1]) < 512) {} }
                    BAR256(2);
                    accum_half(acc, sWhA, sWhB, out + (long long)(t - 1) * HH,
                               (long long)LL * HH, b0, ln, 1, true);
                }
                float psum = reduce32(acc, redw, ln);
                BAR64(3 + wp);   // early partial (ring-lo + h1-lo) in comb
                float hval = tanhf(psum + comb[(t & 1) * 256 + ci] + bias);
                out[(long long)myb * LL * HH + (long long)t * HH + myc] = hval;
                if (write_final && t == LL - 1)
                    out[(long long)BB * LL * HH + BB * HH + myb * HH + myc] = hval;
                __syncwarp();    // this warp's STGs issued
                if (ln == 0) rel_add(&g_flagB[t]);
            }
        }
    }
}

extern "C" void kernel_launch(void* const* d_in, const int* in_sizes, int n_in,
                              void* d_out, int out_size)
{
    const float* x  = (const float*)d_in[0];
    const float* h0 = (const float*)d_in[1];
    const float* Wi = (const float*)d_in[2];
    const float* bi = (const float*)d_in[3];
    const float* Wh = (const float*)d_in[4];
    const float* bh = (const float*)d_in[5];
    float* out = (float*)d_out;

    int write_final = (out_size >= BB * LL * HH + 2 * BB * HH) ? 1 : 0;

    size_t smem = (size_t)(4 * HH * 16)                    // weights 32 KB
                + (size_t)(16 * 32 * 33) * sizeof(float)   // red    ~66 KB
                + (size_t)(2 * 256) * sizeof(float);       // comb     2 KB
    cudaFuncSetAttribute(rnn_kernel,
                         cudaFuncAttributeMaxDynamicSharedMemorySize, (int)smem);

    zero_flags_kernel<<<(LL + 255) / 256, 256>>>();
    rnn_kernel<<<GA + GB, NTHR, smem>>>(x, h0, Wi, bi, Wh, bh, out, write_final);
}

// round 16
// speedup vs baseline: 1.0223x; 1.0114x over previous
#include <cuda_runtime.h>

// ============================================================================
// 2-layer tanh RNN, B=32, L=2048, H=512 — v15: v14-A + v12-B + fast tanh.
//
// 128 persistent CTAs (1/SM), 512 threads (16 warps):
//   CTA 0..63   : layer 0 (A), output cols [cta*8, cta*8+8)
//   CTA 64..127 : layer 1 (B), cols [(cta-64)*8, ...)
// Pair (wp, 8+wp) covers rows 4wp..4wp+3.
//
// Design law (validated v12 vs v13/v14): ONE serial gate per critical warp,
// gate wait filled with ungated work, minimal post-gate segment.
//   A early (0..7):  x-LO 128 FMA2 (ungated) -> gate AL[t-1] -> h-LO 128
//   A late  (8..15): x-HI 128 (ungated fill) -> gate AH[t-1] (+B[t-8] ring
//                    reuse, 8-slack) -> h-HI 128 -> reduce -> +comb -> tanh
//                    -> publish ring (per-warp rel_add)
//   B early (0..7):  gate AL[t]&AH[t] (open; A leads) -> ring full-K 256
//   B late  (8..15): gate B[t-1] -> h1 full-K 256 -> reduce -> +comb -> tanh
//                    -> publish out (per-warp rel_add)
// Flags: AL/AH tgt 256 (per-warp publication, 8 warps x 32 CTAs), B tgt 512.
// Gates: leader-warp poll (w0/w8) + half-CTA named barrier (ids 1/2);
// pair combine via BAR64(3+wp) + comb double buffer (parity t&1).
//
// Fast tanh (publish path): clamp +/-20, e = __expf(2x) (MUFU.EX2),
// tanh = (e-1)/(e+1) via __fdividef. ~60 cyc vs ~180 for tanhf; per-step
// error ~1e-6 (budget 1e-3).
// Dataflow: L0 h -> 8-slot global ring; L1 h -> d_out. __ldcg cross-SM reads.
// ============================================================================

#define BB 32
#define LL 2048
#define HH 512
#define GA 64
#define GB 64
#define NTHR 512

__device__ float g_ring[8 * BB * HH];   // layer-0 h ring, 8 slots, 512 KB
__device__ int   g_flagAL[LL];          // A cols [0,256)   done at t (tgt 256)
__device__ int   g_flagAH[LL];          // A cols [256,512) done at t (tgt 256)
__device__ int   g_flagB[LL];           // B done at t (tgt 512)

__device__ __forceinline__ int acq(const int* p) {
    int v;
    asm volatile("ld.acquire.gpu.global.b32 %0, [%1];" : "=r"(v) : "l"(p) : "memory");
    return v;
}
__device__ __forceinline__ void rel_add(int* p) {
    asm volatile("red.release.gpu.global.add.u32 [%0], %1;"
                 :: "l"(p), "r"(1u) : "memory");
}
#define BAR256(id) asm volatile("bar.sync %0, 256;" :: "r"(id) : "memory")
#define BAR64(id)  asm volatile("bar.sync %0, 64;"  :: "r"(id) : "memory")

#define FMA2(d, a, w) asm volatile("fma.rn.f32x2 %0, %1, %2, %0;" \
                                   : "+l"(d) : "l"(a), "l"(w))

__device__ __forceinline__ unsigned long long pack2(float v) {
    unsigned long long r;
    asm("mov.b64 %0, {%1,%1};" : "=l"(r) : "f"(v));
    return r;
}

// Fast tanh: MUFU.EX2-based, rel err ~1e-6 (per-step budget fine at 1e-3).
__device__ __forceinline__ float tanh_fast(float x) {
    float xc = fminf(fmaxf(x, -20.f), 20.f);
    float e  = __expf(2.f * xc);
    return __fdividef(e - 1.f, e + 1.f);
}

__global__ void zero_flags_kernel() {
    int i = blockIdx.x * blockDim.x + threadIdx.x;
    if (i < LL) { g_flagAL[i] = 0; g_flagAH[i] = 0; g_flagB[i] = 0; }
}

// Full-K accumulation of ONE side: all 16 LDG.128 batched up front (MLP=16).
// acc[b*4+q] packs cols (2q,2q+1) for row b0+b. Weights lane-interleaved:
// [(i4*4+e)*32+ln] = k = 128*i4 + 4*ln + e.
__device__ __forceinline__ void accum_both(
    unsigned long long acc[16],
    const ulonglong2* __restrict__ wA, const ulonglong2* __restrict__ wB,
    const float* __restrict__ p, long long stride, int b0, int ln, bool cg)
{
    float4 v[4][4];   // [i4][b]
    #pragma unroll
    for (int i4 = 0; i4 < 4; i4++)
        #pragma unroll
        for (int b = 0; b < 4; b++) {
            const float4* a = (const float4*)(p + (long long)(b0 + b) * stride
                                              + 128 * i4 + 4 * ln);
            v[i4][b] = cg ? __ldcg(a) : *a;
        }
    #pragma unroll
    for (int i4 = 0; i4 < 4; i4++)
        #pragma unroll
        for (int e = 0; e < 4; e++) {
            ulonglong2 a  = wA[(i4 * 4 + e) * 32 + ln];
            ulonglong2 bq = wB[(i4 * 4 + e) * 32 + ln];
            #pragma unroll
            for (int b = 0; b < 4; b++) {
                float xv = (e == 0) ? v[i4][b].x : (e == 1) ? v[i4][b].y
                         : (e == 2) ? v[i4][b].z : v[i4][b].w;
                unsigned long long xp = pack2(xv);
                FMA2(acc[b * 4 + 0], xp, a.x);
                FMA2(acc[b * 4 + 1], xp, a.y);
                FMA2(acc[b * 4 + 2], xp, bq.x);
                FMA2(acc[b * 4 + 3], xp, bq.y);
            }
        }
}

// Half-K accumulation (hk = 0: k<256, hk = 1: k>=256) of one side, 8 LDG.128.
__device__ __forceinline__ void accum_half(
    unsigned long long acc[16],
    const ulonglong2* __restrict__ wA, const ulonglong2* __restrict__ wB,
    const float* __restrict__ p, long long stride, int b0, int ln,
    int hk, bool cg)
{
    float4 v[2][4];
    #pragma unroll
    for (int j = 0; j < 2; j++) {
        int i4 = 2 * hk + j;
        #pragma unroll
        for (int b = 0; b < 4; b++) {
            const float4* a = (const float4*)(p + (long long)(b0 + b) * stride
                                              + 128 * i4 + 4 * ln);
            v[j][b] = cg ? __ldcg(a) : *a;
        }
    }
    #pragma unroll
    for (int j = 0; j < 2; j++) {
        int i4 = 2 * hk + j;
        #pragma unroll
        for (int e = 0; e < 4; e++) {
            ulonglong2 a  = wA[(i4 * 4 + e) * 32 + ln];
            ulonglong2 bq = wB[(i4 * 4 + e) * 32 + ln];
            #pragma unroll
            for (int b = 0; b < 4; b++) {
                float xv = (e == 0) ? v[j][b].x : (e == 1) ? v[j][b].y
                         : (e == 2) ? v[j][b].z : v[j][b].w;
                unsigned long long xp = pack2(xv);
                FMA2(acc[b * 4 + 0], xp, a.x);
                FMA2(acc[b * 4 + 1], xp, a.y);
                FMA2(acc[b * 4 + 2], xp, bq.x);
                FMA2(acc[b * 4 + 3], xp, bq.y);
            }
        }
    }
}

// Per-warp transpose-reduce over the 32-lane K split.
__device__ __forceinline__ float reduce32(const unsigned long long acc[16],
                                          float* redw, int ln)
{
    #pragma unroll
    for (int i = 0; i < 16; i++) {
        float2 v = *reinterpret_cast<const float2*>(&acc[i]);
        int a = (i >> 2) * 8 + (i & 3) * 2;
        redw[ln * 33 + a]     = v.x;
        redw[ln * 33 + a + 1] = v.y;
    }
    __syncwarp();
    float s0 = 0.f, s1 = 0.f, s2 = 0.f, s3 = 0.f;
    #pragma unroll
    for (int a = 0; a < 32; a += 4) {
        s0 += redw[(a + 0) * 33 + ln];
        s1 += redw[(a + 1) * 33 + ln];
        s2 += redw[(a + 2) * 33 + ln];
        s3 += redw[(a + 3) * 33 + ln];
    }
    __syncwarp();
    return (s0 + s1) + (s2 + s3);
}

__global__ __launch_bounds__(NTHR, 1) void rnn_kernel(
    const float* __restrict__ x,   const float* __restrict__ h0in,
    const float* __restrict__ Wi,  const float* __restrict__ bi,
    const float* __restrict__ Wh,  const float* __restrict__ bh,
    float* __restrict__ out, int write_final)
{
    extern __shared__ float smem[];
    ulonglong2* sWiA = (ulonglong2*)smem;      // [512] Wi cols 0-3
    ulonglong2* sWiB = sWiA + HH;              // [512] Wi cols 4-7
    ulonglong2* sWhA = sWiB + HH;              // [512] Wh cols 0-3
    ulonglong2* sWhB = sWhA + HH;              // [512] Wh cols 4-7
    float*      red  = (float*)(sWhB + HH);    // [16 warps][32][33]
    float*      comb = red + 16 * 32 * 33;     // [2][256] early->late combine

    const int  cta   = blockIdx.x;
    const bool isA   = (cta < GA);
    const int  layer = isA ? 0 : 1;
    const int  c0    = (isA ? cta : cta - GA) * 8;
    const int  tid   = threadIdx.x;
    const int  w     = tid >> 5;
    const int  ln    = tid & 31;
    const int  late  = w >> 3;          // 0 = early, 1 = late (critical)
    const int  wp    = w & 7;           // pair index
    const int  b0    = 4 * wp;

    // ---- stage weight slices once ----
    {
        const float* wi_g = Wi + (size_t)layer * HH * HH + c0;
        const float* wh_g = Wh + (size_t)layer * HH * HH + c0;
        for (int k = tid; k < HH; k += NTHR) {
            int idx = ((k >> 7) * 4 + (k & 3)) * 32 + ((k >> 2) & 31);
            const ulonglong2* ri = (const ulonglong2*)(wi_g + (size_t)k * HH);
            const ulonglong2* rh = (const ulonglong2*)(wh_g + (size_t)k * HH);
            sWiA[idx] = ri[0];  sWiB[idx] = ri[1];
            sWhA[idx] = rh[0];  sWhB[idx] = rh[1];
        }
    }
    __syncthreads();    // one-time; no CTA-wide barrier in the loop

    const int   myb  = b0 + (ln >> 3);
    const int   myc  = c0 + (ln & 7);
    const float bias = bi[layer * HH + myc] + bh[layer * HH + myc];
    float* redw = red + w * (32 * 33);
    const int ci = wp * 32 + ln;

    if (isA) {
        if (!late) {
            // ===== A EARLY: x-LO (ungated) -> gate AL[t-1] -> h-LO =====
            #pragma unroll 1
            for (int t = 0; t < LL; t++) {
                unsigned long long acc[16];
                #pragma unroll
                for (int i = 0; i < 16; i++) acc[i] = 0ull;
                accum_half(acc, sWiA, sWiB, x + (long long)t * HH,
                           (long long)LL * HH, b0, ln, 0, false);
                if (t == 0) {
                    accum_half(acc, sWhA, sWhB, h0in, HH, b0, ln, 0, false);
                } else {
                    if (w == 0) { while (acq(&g_flagAL[t-1]) < 256) {} }
                    BAR256(1);
                    accum_half(acc, sWhA, sWhB,
                               g_ring + ((t - 1) & 7) * (BB * HH),
                               HH, b0, ln, 0, true);
                }
                comb[(t & 1) * 256 + ci] = reduce32(acc, redw, ln);
                BAR64(3 + wp);
            }
        } else {
            // ===== A LATE: x-HI (fill) -> gate AH[t-1] -> h-HI -> publish ===
            #pragma unroll 1
            for (int t = 0; t < LL; t++) {
                unsigned long long acc[16];
                #pragma unroll
                for (int i = 0; i < 16; i++) acc[i] = 0ull;
                accum_half(acc, sWiA, sWiB, x + (long long)t * HH,
                           (long long)LL * HH, b0, ln, 1, false);
                if (t == 0) {
                    accum_half(acc, sWhA, sWhB, h0in, HH, b0, ln, 1, false);
                } else {
                    if (w == 8) {
                        if (t >= 8) { while (acq(&g_flagAH[t-1]) < 256 ||
                                             acq(&g_flagB[t-8])  < 512) {} }
                        else        { while (acq(&g_flagAH[t-1]) < 256) {} }
                    }
                    BAR256(2);
                    accum_half(acc, sWhA, sWhB,
                               g_ring + ((t - 1) & 7) * (BB * HH),
                               HH, b0, ln, 1, true);
                }
                float psum = reduce32(acc, redw, ln);
                BAR64(3 + wp);   // early partial (x-lo + h-lo) in comb
                float hval = tanh_fast(psum + comb[(t & 1) * 256 + ci] + bias);
                g_ring[(t & 7) * (BB * HH) + myb * HH + myc] = hval;
                if (write_final && t == LL - 1)
                    out[(long long)BB * LL * HH + myb * HH + myc] = hval;
                __syncwarp();    // this warp's STGs issued
                if (ln == 0)
                    rel_add(cta < 32 ? &g_flagAL[t] : &g_flagAH[t]);
            }
        }
    } else {
        if (!late) {
            // ===== B EARLY: gate AL&AH[t] (open; A leads) -> ring full-K ====
            #pragma unroll 1
            for (int t = 0; t < LL; t++) {
                unsigned long long acc[16];
                #pragma unroll
                for (int i = 0; i < 16; i++) acc[i] = 0ull;
                if (w == 0) { while (acq(&g_flagAL[t]) < 256 ||
                                     acq(&g_flagAH[t]) < 256) {} }
                BAR256(1);
                accum_both(acc, sWiA, sWiB, g_ring + (t & 7) * (BB * HH),
                           HH, b0, ln, true);
                comb[(t & 1) * 256 + ci] = reduce32(acc, redw, ln);
                BAR64(3 + wp);
            }
        } else {
            // ===== B LATE: gate B[t-1] -> h1 full-K -> publish =====
            #pragma unroll 1
            for (int t = 0; t < LL; t++) {
                unsigned long long acc[16];
                #pragma unroll
                for (int i = 0; i < 16; i++) acc[i] = 0ull;
                if (t == 0) {
                    accum_both(acc, sWhA, sWhB, h0in + BB * HH,
                               HH, b0, ln, false);
                } else {
                    if (w == 8) { while (acq(&g_flagB[t-1]) < 512) {} }
                    BAR256(2);
                    accum_both(acc, sWhA, sWhB, out + (long long)(t - 1) * HH,
                               (long long)LL * HH, b0, ln, true);
                }
                float psum = reduce32(acc, redw, ln);
                BAR64(3 + wp);   // early partial (ring) ready in comb
                float hval = tanh_fast(psum + comb[(t & 1) * 256 + ci] + bias);
                out[(long long)myb * LL * HH + (long long)t * HH + myc] = hval;
                if (write_final && t == LL - 1)
                    out[(long long)BB * LL * HH + BB * HH + myb * HH + myc] = hval;
                __syncwarp();    // this warp's STGs issued
                if (ln == 0) rel_add(&g_flagB[t]);
            }
        }
    }
}

extern "C" void kernel_launch(void* const* d_in, const int* in_sizes, int n_in,
                              void* d_out, int out_size)
{
    const float* x  = (const float*)d_in[0];
    const float* h0 = (const float*)d_in[1];
    const float* Wi = (const float*)d_in[2];
    const float* bi = (const float*)d_in[3];
    const float* Wh = (const float*)d_in[4];
    const float* bh = (const float*)d_in[5];
    float* out = (float*)d_out;

    int write_final = (out_size >= BB * LL * HH + 2 * BB * HH) ? 1 : 0;

    size_t smem = (size_t)(4 * HH * 16)                    // weights 32 KB
                + (size_t)(16 * 32 * 33) * sizeof(float)   // red    ~66 KB
                + (size_t)(2 * 256) * sizeof(float);       // comb     2 KB
    cudaFuncSetAttribute(rnn_kernel,
                         cudaFuncAttributeMaxDynamicSharedMemorySize, (int)smem);

    zero_flags_kernel<<<(LL + 255) / 256, 256>>>();
    rnn_kernel<<<GA + GB, NTHR, smem>>>(x, h0, Wi, bi, Wh, bh, out, write_final);
}